// round 6
// baseline (speedup 1.0000x reference)
#include <cuda_runtime.h>
#include <cuda_fp16.h>
#include <math.h>
#include <stdint.h>

#define N_TOK 2048
#define D_DIM 1024
#define E_NUM 8
#define K_TOP 2
#define H_DIM 2048
#define NK (N_TOK*K_TOP)
#define Z_COEF 1e-4f

// ---------------- fp16 scratch (device globals; no allocs allowed) ----------------
__device__ __half g_x16[(size_t)N_TOK*D_DIM];
__device__ __half g_h16[(size_t)NK*H_DIM];
__device__ __half g_hsh16[(size_t)N_TOK*H_DIM];
__device__ float  g_pairout[(size_t)NK*D_DIM];

// ---------------- router scratch ----------------
__device__ int   g_topk[NK];
__device__ float g_wts[NK];
__device__ int   g_cnt[E_NUM];
__device__ int   g_off[E_NUM];
__device__ int   g_cursor[E_NUM];
__device__ int   g_rowtok[NK];
__device__ float g_roww[NK];
__device__ int   g_pos[NK];
__device__ float g_psum[E_NUM];
__device__ float g_z2;

// ============================ PTX helpers ============================
__device__ __forceinline__ uint32_t smem_u32(const void* p){
    uint32_t a;
    asm("{ .reg .u64 t; cvta.to.shared.u64 t, %1; cvt.u32.u64 %0, t; }" : "=r"(a) : "l"(p));
    return a;
}
__device__ __forceinline__ void cp16(uint32_t dst, const void* src, uint32_t sz){
    asm volatile("cp.async.cg.shared.global [%0], [%1], 16, %2;"
                 :: "r"(dst), "l"(src), "r"(sz) : "memory");
}
__device__ __forceinline__ void cp_commit(){ asm volatile("cp.async.commit_group;" ::: "memory"); }
__device__ __forceinline__ void ldsm4(uint32_t* r, uint32_t addr){
    asm volatile("ldmatrix.sync.aligned.m8n8.x4.shared.b16 {%0,%1,%2,%3}, [%4];"
                 : "=r"(r[0]), "=r"(r[1]), "=r"(r[2]), "=r"(r[3]) : "r"(addr));
}
__device__ __forceinline__ void mma16816(float* c, const uint32_t* a, const uint32_t* b){
    asm volatile("mma.sync.aligned.m16n8k16.row.col.f32.f16.f16.f32 "
                 "{%0,%1,%2,%3}, {%4,%5,%6,%7}, {%8,%9}, {%0,%1,%2,%3};"
                 : "+f"(c[0]), "+f"(c[1]), "+f"(c[2]), "+f"(c[3])
                 : "r"(a[0]), "r"(a[1]), "r"(a[2]), "r"(a[3]), "r"(b[0]), "r"(b[1]));
}
#define CP_WAIT(N) asm volatile("cp.async.wait_group %0;" :: "n"(N) : "memory")

__device__ __forceinline__ uint4 pack8(const float4 a, const float4 b){
    uint4 v;
    __half2 h0 = __floats2half2_rn(a.x, a.y);
    __half2 h1 = __floats2half2_rn(a.z, a.w);
    __half2 h2 = __floats2half2_rn(b.x, b.y);
    __half2 h3 = __floats2half2_rn(b.z, b.w);
    v.x = *(uint32_t*)&h0; v.y = *(uint32_t*)&h1;
    v.z = *(uint32_t*)&h2; v.w = *(uint32_t*)&h3;
    return v;
}

// ============================ prepass: x fp32->fp16 + per-launch init ============================
__global__ void convert_x_kernel(const float4* __restrict__ src, uint2* __restrict__ dst, int n4){
    int i = blockIdx.x*256 + threadIdx.x;
    if (blockIdx.x == 0) {
        int t = threadIdx.x;
        if (t < E_NUM) { g_cnt[t] = 0; g_cursor[t] = 0; g_psum[t] = 0.f; }
        if (t == E_NUM) g_z2 = 0.f;
    }
    if (i >= n4) return;
    float4 v = src[i];
    __half2 a = __floats2half2_rn(v.x, v.y);
    __half2 b = __floats2half2_rn(v.z, v.w);
    uint2 o;
    o.x = *(uint32_t*)&a;
    o.y = *(uint32_t*)&b;
    dst[i] = o;
}

// ============================ router (fp32, exact) ============================
__global__ void router_kernel(const float* __restrict__ x,
                              const float* __restrict__ rw,
                              const float* __restrict__ rb) {
    int n = blockIdx.x;
    int tid = threadIdx.x;
    __shared__ float xs[D_DIM];
    __shared__ float lg[E_NUM];
    const float* xrow = x + (size_t)n * D_DIM;
    for (int i = tid; i < D_DIM; i += 256) xs[i] = xrow[i];
    __syncthreads();

    int w = tid >> 5, lane = tid & 31;
    const float* wr = rw + (size_t)w * D_DIM;
    float s = 0.f;
    for (int i = lane; i < D_DIM; i += 32) s += xs[i] * wr[i];
    #pragma unroll
    for (int o = 16; o; o >>= 1) s += __shfl_xor_sync(0xffffffff, s, o);
    if (lane == 0) lg[w] = s;
    __syncthreads();

    if (tid == 0) {
        float l[E_NUM];
        #pragma unroll
        for (int e = 0; e < E_NUM; e++) l[e] = lg[e];

        int e0 = 0; float b0 = l[0] + rb[0];
        #pragma unroll
        for (int e = 1; e < E_NUM; e++) { float be = l[e] + rb[e]; if (be > b0) { b0 = be; e0 = e; } }
        int e1 = -1; float b1 = -1e30f;
        #pragma unroll
        for (int e = 0; e < E_NUM; e++) {
            if (e == e0) continue;
            float be = l[e] + rb[e];
            if (be > b1) { b1 = be; e1 = e; }
        }

        float l0 = l[e0], l1 = l[e1];
        float m2 = fmaxf(l0, l1);
        float w0 = expf(l0 - m2), w1 = expf(l1 - m2);
        float inv = 1.f / (w0 + w1);
        w0 *= inv; w1 *= inv;

        float mx = l[0];
        #pragma unroll
        for (int e = 1; e < E_NUM; e++) mx = fmaxf(mx, l[e]);
        float pe[E_NUM]; float se = 0.f;
        #pragma unroll
        for (int e = 0; e < E_NUM; e++) { pe[e] = expf(l[e] - mx); se += pe[e]; }
        float z = mx + logf(se);
        atomicAdd(&g_z2, z * z);
        float invse = 1.f / se;
        #pragma unroll
        for (int e = 0; e < E_NUM; e++) atomicAdd(&g_psum[e], pe[e] * invse);

        atomicAdd(&g_cnt[e0], 1);
        atomicAdd(&g_cnt[e1], 1);
        g_topk[n * 2 + 0] = e0; g_topk[n * 2 + 1] = e1;
        g_wts[n * 2 + 0]  = w0; g_wts[n * 2 + 1]  = w1;
    }
}

// ============================ finalize + scatter (single block) ============================
__global__ void finalize_scatter_kernel(float* __restrict__ out_scalars, int have_scalars) {
    if (threadIdx.x == 0) {
        int acc = 0;
        for (int e = 0; e < E_NUM; e++) { g_off[e] = acc; acc += g_cnt[e]; }
        if (have_scalars) {
            float lb = 0.f;
            for (int e = 0; e < E_NUM; e++)
                lb += (g_psum[e] / (float)N_TOK) * ((float)g_cnt[e] / (float)N_TOK);
            lb *= (float)E_NUM;
            out_scalars[0] = 0.f;
            out_scalars[1] = g_z2 / (float)N_TOK * Z_COEF;
            out_scalars[2] = lb;
        }
    }
    __syncthreads();
    for (int i = threadIdx.x; i < NK; i += 256) {
        int e = g_topk[i];
        int p = g_off[e] + atomicAdd(&g_cursor[e], 1);
        g_rowtok[p] = i >> 1;
        g_roww[p]   = g_wts[i];
        g_pos[i]    = p;
    }
}

// ============================ tensor-core GEMMs (mma.sync HMMA) ============================
// Tile: BM=128, BN=64, BK=64. 8 warps as 4(M) x 2(N); warp tile 32x32.
// A (fp16) via cp.async; W (fp32) via LDG->cvt->STS fp16, 1 stage ahead.
// smem rows = 64 halves + 8 pad = 144 bytes.
#define LDR 144
#define GU_G 18432
#define GU_U 27648
#define GU_STG 36864
#define GU_SMEM (2*GU_STG)
#define DN_B 18432
#define DN_STG 27648
#define DN_SMEM (2*DN_STG)

__global__ __launch_bounds__(256) void gateup_mma(
    const float* __restrict__ GateW, const float* __restrict__ UpW,
    const float* __restrict__ ShG,   const float* __restrict__ ShU)
{
    int grp = blockIdx.z;
    bool routed = grp < E_NUM;
    int rbase = routed ? g_off[grp] : 0;
    int rcnt  = routed ? g_cnt[grp] : N_TOK;
    int m0 = blockIdx.y * 128;
    if (m0 >= rcnt) return;
    int n0 = blockIdx.x * 64;

    const float* Wg = routed ? GateW + (size_t)grp * H_DIM * D_DIM : ShG;
    const float* Wu = routed ? UpW   + (size_t)grp * H_DIM * D_DIM : ShU;
    __half* Hout = routed ? g_h16 : g_hsh16;

    extern __shared__ __align__(16) char smem[];
    uint32_t sb = smem_u32(smem);
    int tid = threadIdx.x;

    // A: thread t -> row t>>1, half-row (t&1): 4 x cp16
    int rowA = tid >> 1, halfA = tid & 1;
    const __half* asrc = g_x16;
    uint32_t av = 0;
    if (m0 + rowA < rcnt) {
        int tk = routed ? g_rowtok[rbase + m0 + rowA] : m0 + rowA;
        asrc = g_x16 + (size_t)tk * D_DIM + halfA * 32;
        av = 16;
    }
    uint32_t dA = sb + rowA * LDR + halfA * 64;

    // W: thread t -> row t>>2 (0..63), quarter q=t&3 covers halves [q*16, q*16+16)
    int rowW = tid >> 2, q = tid & 3;
    const float* gw = Wg + (size_t)(n0 + rowW) * D_DIM + q * 16;
    const float* uw = Wu + (size_t)(n0 + rowW) * D_DIM + q * 16;
    uint32_t dG = GU_G + rowW * LDR + q * 32;   // byte offsets within smem[]
    uint32_t dU = GU_U + rowW * LDR + q * 32;

    float4 wg0, wg1, wg2, wg3, wu0, wu1, wu2, wu3;
    auto ldg_w = [&](int s) {
        const float4* gp = (const float4*)(gw + s * 64);
        const float4* up = (const float4*)(uw + s * 64);
        wg0 = gp[0]; wg1 = gp[1]; wg2 = gp[2]; wg3 = gp[3];
        wu0 = up[0]; wu1 = up[1]; wu2 = up[2]; wu3 = up[3];
    };
    auto sts_w = [&](int buf) {
        uint32_t o = (uint32_t)buf * GU_STG;
        *(uint4*)(smem + dG + o)      = pack8(wg0, wg1);
        *(uint4*)(smem + dG + o + 16) = pack8(wg2, wg3);
        *(uint4*)(smem + dU + o)      = pack8(wu0, wu1);
        *(uint4*)(smem + dU + o + 16) = pack8(wu2, wu3);
    };
    auto cp_a = [&](int s) {
        uint32_t o = (uint32_t)(s & 1) * GU_STG;
        const __half* a = asrc + s * 64;
        #pragma unroll
        for (int j = 0; j < 4; j++)
            cp16(dA + o + j * 16, a + j * 8, av);
        cp_commit();
    };

    const int S = D_DIM / 64;   // 16
    ldg_w(0); sts_w(0); cp_a(0);
    ldg_w(1); cp_a(1);

    int warp = tid >> 5, lane = tid & 31;
    int wm = warp & 3, wn = warp >> 2;
    int g = lane >> 3;
    int brow = ((g >> 1) << 3) + (lane & 7);
    int bks = (g & 1) << 4;

    float cg[2][4][4] = {}, cu[2][4][4] = {};

    #pragma unroll 1
    for (int s = 0; s < S; s++) {
        if (s + 1 < S) CP_WAIT(1);
        else           CP_WAIT(0);
        __syncthreads();
        uint32_t o = sb + (uint32_t)(s & 1) * GU_STG;

        #pragma unroll
        for (int kt = 0; kt < 4; kt++) {
            uint32_t a[2][4];
            #pragma unroll
            for (int mt = 0; mt < 2; mt++)
                ldsm4(a[mt], o + (wm * 32 + mt * 16 + (lane & 15)) * LDR + kt * 32 + (lane >> 4) * 16);
            uint32_t bg[2][4], bu[2][4];
            #pragma unroll
            for (int nt = 0; nt < 2; nt++) {
                uint32_t ro = (wn * 32 + nt * 16 + brow) * LDR + kt * 32 + bks;
                ldsm4(bg[nt], o + GU_G + ro);
                ldsm4(bu[nt], o + GU_U + ro);
            }
            #pragma unroll
            for (int mt = 0; mt < 2; mt++)
                #pragma unroll
                for (int nt = 0; nt < 2; nt++) {
                    mma16816(cg[mt][nt * 2 + 0], a[mt], &bg[nt][0]);
                    mma16816(cg[mt][nt * 2 + 1], a[mt], &bg[nt][2]);
                    mma16816(cu[mt][nt * 2 + 0], a[mt], &bu[nt][0]);
                    mma16816(cu[mt][nt * 2 + 1], a[mt], &bu[nt][2]);
                }
        }

        if (s + 1 < S) sts_w((s + 1) & 1);
        __syncthreads();
        if (s + 2 < S) { cp_a(s + 2); ldg_w(s + 2); }
    }

    #pragma unroll
    for (int mt = 0; mt < 2; mt++) {
        int rbaserow = m0 + wm * 32 + mt * 16 + (lane >> 2);
        #pragma unroll
        for (int h = 0; h < 2; h++) {
            int r = rbaserow + h * 8;
            if (r >= rcnt) continue;
            __half* hp = Hout + (size_t)(rbase + r) * H_DIM + n0 + wn * 32 + (lane & 3) * 2;
            #pragma unroll
            for (int j = 0; j < 4; j++) {
                float g0 = cg[mt][j][h * 2 + 0], g1 = cg[mt][j][h * 2 + 1];
                float u0 = cu[mt][j][h * 2 + 0], u1 = cu[mt][j][h * 2 + 1];
                float h0 = g0 * u0 / (1.f + __expf(-g0));
                float h1 = g1 * u1 / (1.f + __expf(-g1));
                *(__half2*)(hp + j * 8) = __floats2half2_rn(h0, h1);
            }
        }
    }
}

__global__ __launch_bounds__(256) void down_mma(
    const float* __restrict__ DownW, const float* __restrict__ ShD,
    float* __restrict__ Out)
{
    int grp = blockIdx.z;
    bool routed = grp < E_NUM;
    int rbase = routed ? g_off[grp] : 0;
    int rcnt  = routed ? g_cnt[grp] : N_TOK;
    int m0 = blockIdx.y * 128;
    if (m0 >= rcnt) return;
    int n0 = blockIdx.x * 64;

    const float* Wd  = routed ? DownW + (size_t)grp * D_DIM * H_DIM : ShD;
    const __half* Hin = routed ? g_h16 : g_hsh16;

    extern __shared__ __align__(16) char smem[];
    uint32_t sb = smem_u32(smem);
    int tid = threadIdx.x;

    int rowA = tid >> 1, halfA = tid & 1;
    const __half* asrc = Hin;
    uint32_t av = 0;
    if (m0 + rowA < rcnt) {
        asrc = Hin + (size_t)(rbase + m0 + rowA) * H_DIM + halfA * 32;
        av = 16;
    }
    uint32_t dA = sb + rowA * LDR + halfA * 64;

    int rowW = tid >> 2, q = tid & 3;
    const float* dw = Wd + (size_t)(n0 + rowW) * H_DIM + q * 16;
    uint32_t dB = DN_B + rowW * LDR + q * 32;

    float4 wd0, wd1, wd2, wd3;
    auto ldg_w = [&](int s) {
        const float4* p = (const float4*)(dw + s * 64);
        wd0 = p[0]; wd1 = p[1]; wd2 = p[2]; wd3 = p[3];
    };
    auto sts_w = [&](int buf) {
        uint32_t o = (uint32_t)buf * DN_STG;
        *(uint4*)(smem + dB + o)      = pack8(wd0, wd1);
        *(uint4*)(smem + dB + o + 16) = pack8(wd2, wd3);
    };
    auto cp_a = [&](int s) {
        uint32_t o = (uint32_t)(s & 1) * DN_STG;
        const __half* a = asrc + s * 64;
        #pragma unroll
        for (int j = 0; j < 4; j++)
            cp16(dA + o + j * 16, a + j * 8, av);
        cp_commit();
    };

    const int S = H_DIM / 64;   // 32
    ldg_w(0); sts_w(0); cp_a(0);
    ldg_w(1); cp_a(1);

    int warp = tid >> 5, lane = tid & 31;
    int wm = warp & 3, wn = warp >> 2;
    int g = lane >> 3;
    int brow = ((g >> 1) << 3) + (lane & 7);
    int bks = (g & 1) << 4;

    float c[2][4][4] = {};

    #pragma unroll 1
    for (int s = 0; s < S; s++) {
        if (s + 1 < S) CP_WAIT(1);
        else           CP_WAIT(0);
        __syncthreads();
        uint32_t o = sb + (uint32_t)(s & 1) * DN_STG;

        #pragma unroll
        for (int kt = 0; kt < 4; kt++) {
            uint32_t a[2][4];
            #pragma unroll
            for (int mt = 0; mt < 2; mt++)
                ldsm4(a[mt], o + (wm * 32 + mt * 16 + (lane & 15)) * LDR + kt * 32 + (lane >> 4) * 16);
            uint32_t b[2][4];
            #pragma unroll
            for (int nt = 0; nt < 2; nt++)
                ldsm4(b[nt], o + DN_B + (wn * 32 + nt * 16 + brow) * LDR + kt * 32 + bks);
            #pragma unroll
            for (int mt = 0; mt < 2; mt++)
                #pragma unroll
                for (int nt = 0; nt < 2; nt++) {
                    mma16816(c[mt][nt * 2 + 0], a[mt], &b[nt][0]);
                    mma16816(c[mt][nt * 2 + 1], a[mt], &b[nt][2]);
                }
        }

        if (s + 1 < S) sts_w((s + 1) & 1);
        __syncthreads();
        if (s + 2 < S) { cp_a(s + 2); ldg_w(s + 2); }
    }

    #pragma unroll
    for (int mt = 0; mt < 2; mt++) {
        int rbaserow = m0 + wm * 32 + mt * 16 + (lane >> 2);
        #pragma unroll
        for (int h = 0; h < 2; h++) {
            int r = rbaserow + h * 8;
            if (r >= rcnt) continue;
            float w = routed ? g_roww[rbase + r] : 1.f;
            float* op = (routed ? g_pairout + (size_t)(rbase + r) * D_DIM
                                : Out + (size_t)r * D_DIM)
                        + n0 + wn * 32 + (lane & 3) * 2;
            #pragma unroll
            for (int j = 0; j < 4; j++) {
                float2 v = make_float2(c[mt][j][h * 2 + 0] * w, c[mt][j][h * 2 + 1] * w);
                *(float2*)(op + j * 8) = v;
            }
        }
    }
}

// ============================ combine ============================
__global__ void combine_kernel(float* __restrict__ out) {
    int i4 = blockIdx.x * 256 + threadIdx.x;
    const int total4 = N_TOK * D_DIM / 4;
    if (i4 >= total4) return;
    int n  = i4 / (D_DIM / 4);
    int d4 = i4 % (D_DIM / 4);
    int p0 = g_pos[n * 2 + 0];
    int p1 = g_pos[n * 2 + 1];
    const float4* pr = (const float4*)g_pairout;
    float4 o = ((float4*)out)[i4];
    float4 a = pr[(size_t)p0 * (D_DIM / 4) + d4];
    float4 b = pr[(size_t)p1 * (D_DIM / 4) + d4];
    o.x += a.x + b.x; o.y += a.y + b.y; o.z += a.z + b.z; o.w += a.w + b.w;
    ((float4*)out)[i4] = o;
}

// ============================ launch ============================
extern "C" void kernel_launch(void* const* d_in, const int* in_sizes, int n_in,
                              void* d_out, int out_size) {
    const float* x      = (const float*)d_in[0];
    const float* rw     = (const float*)d_in[1];
    const float* rb     = (const float*)d_in[2];
    const float* gate_w = (const float*)d_in[3];
    const float* up_w   = (const float*)d_in[4];
    const float* down_w = (const float*)d_in[5];
    const float* shg    = (const float*)d_in[6];
    const float* shu    = (const float*)d_in[7];
    const float* shd    = (const float*)d_in[8];
    float* out = (float*)d_out;

    const int hid_elems = N_TOK * D_DIM;
    int have_scalars = (out_size >= hid_elems + 3) ? 1 : 0;

    void* p_x16;
    cudaGetSymbolAddress(&p_x16, g_x16);

    cudaFuncSetAttribute(gateup_mma, cudaFuncAttributeMaxDynamicSharedMemorySize, GU_SMEM);
    cudaFuncSetAttribute(down_mma,   cudaFuncAttributeMaxDynamicSharedMemorySize, DN_SMEM);

    const int n4_x = N_TOK * D_DIM / 4;
    convert_x_kernel<<<n4_x / 256, 256>>>((const float4*)x, (uint2*)p_x16, n4_x);

    router_kernel<<<N_TOK, 256>>>(x, rw, rb);
    finalize_scatter_kernel<<<1, 256>>>(out + hid_elems, have_scalars);

    gateup_mma<<<dim3(H_DIM / 64, 16, 9), 256, GU_SMEM>>>(gate_w, up_w, shg, shu);
    down_mma<<<dim3(D_DIM / 64, 16, 9), 256, DN_SMEM>>>(down_w, shd, out);

    combine_kernel<<<(N_TOK * D_DIM / 4 + 255) / 256, 256>>>(out);
}